// round 4
// baseline (speedup 1.0000x reference)
#include <cuda_runtime.h>
#include <cuda_bf16.h>
#include <cstdint>

// HyperspectralAttention collapses (per-head dim == 1 => softmax == 1) to
//   out = W_proj @ ( illu * ( (0.6*W_v_spec + 0.4*W_v_spat) @ x ) )
// Two 64 x 262144 x 64 GEMMs on warp-level mma.sync (bf16 3-way split:
// Ah*Bh + Ah*Bl + Al*Bh => fp32-equivalent accuracy).
//
// R4: 256 threads/CTA (8 warps), each warp = 32 output rows x 32 pixels.
// illu prefetched via cp.async into padded smem during GEMM1 (epilogue is
// smem-local). 2 CTAs/SM (reg-capped at 128) -> 16 warps/SM.

#define TPB 256
#define TP  128

// smem byte offsets
#define SM_WMH 0u
#define SM_WML 8192u
#define SM_WPH 16384u
#define SM_WPL 24576u
#define SM_XH  32768u
#define SM_XL  49152u
#define SM_ILL 65536u              // 64 rows x 132 floats (padded) = 33792B
#define ILL_STRIDE 132
#define SM_TOTAL (65536 + 64 * ILL_STRIDE * 4)

__device__ __forceinline__ uint32_t smem_u32(const void* p) {
    uint32_t a;
    asm("{ .reg .u64 t; cvta.to.shared.u64 t, %1; cvt.u32.u64 %0, t; }"
        : "=r"(a) : "l"(p));
    return a;
}
__device__ __forceinline__ void cp_async16(uint32_t dst, const void* src) {
    asm volatile("cp.async.cg.shared.global [%0], [%1], 16;"
                 :: "r"(dst), "l"(src) : "memory");
}
__device__ __forceinline__ void cp_commit() {
    asm volatile("cp.async.commit_group;" ::: "memory");
}
__device__ __forceinline__ void cp_wait0() {
    asm volatile("cp.async.wait_group 0;" ::: "memory");
}
__device__ __forceinline__ void ldsm4(uint32_t addr, uint32_t r[4]) {
    asm volatile("ldmatrix.sync.aligned.m8n8.x4.shared.b16 {%0,%1,%2,%3}, [%4];"
                 : "=r"(r[0]), "=r"(r[1]), "=r"(r[2]), "=r"(r[3]) : "r"(addr));
}
__device__ __forceinline__ void ldsm4t(uint32_t addr, uint32_t r[4]) {
    asm volatile("ldmatrix.sync.aligned.m8n8.x4.trans.shared.b16 {%0,%1,%2,%3}, [%4];"
                 : "=r"(r[0]), "=r"(r[1]), "=r"(r[2]), "=r"(r[3]) : "r"(addr));
}
__device__ __forceinline__ void mma16816(float c[4], const uint32_t a[4],
                                         uint32_t b0, uint32_t b1) {
    asm volatile("mma.sync.aligned.m16n8k16.row.col.f32.bf16.bf16.f32 "
                 "{%0,%1,%2,%3}, {%4,%5,%6,%7}, {%8,%9}, {%0,%1,%2,%3};"
                 : "+f"(c[0]), "+f"(c[1]), "+f"(c[2]), "+f"(c[3])
                 : "r"(a[0]), "r"(a[1]), "r"(a[2]), "r"(a[3]), "r"(b0), "r"(b1));
}
__device__ __forceinline__ void split2(float v0, float v1, uint32_t& hi, uint32_t& lo) {
    __nv_bfloat16 h0 = __float2bfloat16(v0);
    __nv_bfloat16 h1 = __float2bfloat16(v1);
    __nv_bfloat162 hp, lp;
    hp.x = h0; hp.y = h1;
    lp.x = __float2bfloat16(v0 - __bfloat162float(h0));
    lp.y = __float2bfloat16(v1 - __bfloat162float(h1));
    hi = *reinterpret_cast<uint32_t*>(&hp);
    lo = *reinterpret_cast<uint32_t*>(&lp);
}

// One 32x32x64 sub-GEMM: rows [mhalf*32, +32), pixels [pbase, +32).
// acc[2][4][4]: mt = 16-row tile, nt = 8-px tile.
__device__ __forceinline__ void gemm32(uint32_t sb, uint32_t whOff, uint32_t wlOff,
                                       int lane, int mhalf, int pbase,
                                       float acc[2][4][4]) {
    const uint32_t arow = ((lane >> 3) & 1) * 8 + (lane & 7);
    const uint32_t asw  = (uint32_t)(lane & 7) << 4;
    const uint32_t mbase = (uint32_t)(mhalf * 32);
    #pragma unroll
    for (int kc = 0; kc < 4; kc++) {
        const uint32_t acol = ((uint32_t)(kc * 32 + ((lane >> 4) & 1) * 16)) ^ asw;
        uint32_t ah[2][4], al[2][4];
        #pragma unroll
        for (int mt = 0; mt < 2; mt++) {
            const uint32_t off = (mbase + mt * 16 + arow) * 128 + acol;
            ldsm4(sb + whOff + off, ah[mt]);
            ldsm4(sb + wlOff + off, al[mt]);
        }
        const uint32_t brow = kc * 16 + (lane & 15);
        const uint32_t bsw  = (brow & 7) << 4;
        uint32_t bh[2][4], bl[2][4];
        #pragma unroll
        for (int pr = 0; pr < 2; pr++) {
            const uint32_t ncol = pbase + pr * 16 + ((lane >> 4) & 1) * 8;
            const uint32_t off  = brow * 256 + (((uint32_t)(2 * ncol)) ^ bsw);
            ldsm4t(sb + SM_XH + off, bh[pr]);
            ldsm4t(sb + SM_XL + off, bl[pr]);
        }
        #pragma unroll
        for (int mt = 0; mt < 2; mt++)
            #pragma unroll
            for (int nt = 0; nt < 4; nt++) {
                const uint32_t b0h = bh[nt >> 1][(nt & 1) * 2];
                const uint32_t b1h = bh[nt >> 1][(nt & 1) * 2 + 1];
                const uint32_t b0l = bl[nt >> 1][(nt & 1) * 2];
                const uint32_t b1l = bl[nt >> 1][(nt & 1) * 2 + 1];
                mma16816(acc[mt][nt], ah[mt], b0h, b1h);
                mma16816(acc[mt][nt], ah[mt], b0l, b1l);
                mma16816(acc[mt][nt], al[mt], b0h, b1h);
            }
    }
}

__global__ __launch_bounds__(TPB, 2) void fused_hmma2(
    const float* __restrict__ x, const float* __restrict__ illu,
    const float* __restrict__ wvspec, const float* __restrict__ wvspat,
    const float* __restrict__ wproj, float* __restrict__ out)
{
    extern __shared__ char smem[];
    const uint32_t sb = smem_u32(smem);
    const int tid = threadIdx.x, lane = tid & 31, w = tid >> 5;
    const int mhalf = w & 1, pbase = (w >> 1) * 32;

    const int gbase = blockIdx.x * TP;
    const int b  = gbase >> 16;
    const int po = gbase & 0xFFFF;
    const size_t base = (size_t)b * 4194304 + (size_t)po;
    const float* xb = x    + base;
    const float* ib = illu + base;
    float*       ob = out  + base;

    // ---- illu -> smem via cp.async (completes during GEMM1) ----
    for (int i = tid; i < 2048; i += TPB) {
        const int c = i >> 5, p4 = (i & 31) * 4;
        cp_async16(sb + SM_ILL + (uint32_t)(c * ILL_STRIDE + p4) * 4,
                   ib + (size_t)c * 65536 + p4);
    }
    cp_commit();

    // ---- weights -> smem bf16 hi/lo, [o][c] rows of 128B, XOR swizzle ----
    for (int i = tid; i < 4096; i += TPB) {
        const int o = i >> 6, c = i & 63;
        const uint32_t off = (uint32_t)(o * 128) +
                             (((uint32_t)(2 * c)) ^ ((uint32_t)(o & 7) << 4));
        const float wm = 0.6f * wvspec[i] + 0.4f * wvspat[i];
        __nv_bfloat16 h = __float2bfloat16(wm);
        *(__nv_bfloat16*)(smem + SM_WMH + off) = h;
        *(__nv_bfloat16*)(smem + SM_WML + off) =
            __float2bfloat16(wm - __bfloat162float(h));
        const float wp = wproj[i];
        h = __float2bfloat16(wp);
        *(__nv_bfloat16*)(smem + SM_WPH + off) = h;
        *(__nv_bfloat16*)(smem + SM_WPL + off) =
            __float2bfloat16(wp - __bfloat162float(h));
    }
    // ---- X tile -> smem bf16 hi/lo, [c][p] rows of 256B, XOR swizzle ----
    for (int i = tid; i < 2048; i += TPB) {
        const int c = i >> 5, p = (i & 31) * 4;
        const float4 v = *(const float4*)(xb + (size_t)c * 65536 + p);
        uint32_t h0, l0, h1, l1;
        split2(v.x, v.y, h0, l0);
        split2(v.z, v.w, h1, l1);
        const uint32_t off = (uint32_t)(c * 256) +
                             (((uint32_t)(2 * p)) ^ ((uint32_t)(c & 7) << 4));
        *(uint2*)(smem + SM_XH + off) = make_uint2(h0, h1);
        *(uint2*)(smem + SM_XL + off) = make_uint2(l0, l1);
    }
    __syncthreads();

    float acc[2][4][4];
    #pragma unroll
    for (int mt = 0; mt < 2; mt++)
        #pragma unroll
        for (int nt = 0; nt < 4; nt++)
            #pragma unroll
            for (int q = 0; q < 4; q++) acc[mt][nt][q] = 0.0f;

    // ---- GEMM1: D1 = Wmix @ X (illu cp.async in flight underneath) ----
    gemm32(sb, SM_WMH, SM_WML, lane, mhalf, pbase, acc);

    cp_wait0();
    __syncthreads();     // illu visible; everyone done reading X

    // ---- epilogue 1: T = illu * D1, split, back into X buffers ----
    const int g = lane >> 2, t = lane & 3;
    const float* ILLF = (const float*)(smem + SM_ILL);
    #pragma unroll
    for (int mt = 0; mt < 2; mt++)
        #pragma unroll
        for (int nt = 0; nt < 4; nt++) {
            const int r0 = mhalf * 32 + mt * 16 + g, r1 = r0 + 8;
            const int pp = pbase + nt * 8 + 2 * t;
            const float2 i0 = *(const float2*)&ILLF[r0 * ILL_STRIDE + pp];
            const float2 i1 = *(const float2*)&ILLF[r1 * ILL_STRIDE + pp];
            uint32_t h, l;
            split2(acc[mt][nt][0] * i0.x, acc[mt][nt][1] * i0.y, h, l);
            const uint32_t off0 = (uint32_t)(r0 * 256) +
                                  (((uint32_t)(2 * pp)) ^ ((uint32_t)(r0 & 7) << 4));
            *(uint32_t*)(smem + SM_XH + off0) = h;
            *(uint32_t*)(smem + SM_XL + off0) = l;
            split2(acc[mt][nt][2] * i1.x, acc[mt][nt][3] * i1.y, h, l);
            const uint32_t off1 = (uint32_t)(r1 * 256) +
                                  (((uint32_t)(2 * pp)) ^ ((uint32_t)(r1 & 7) << 4));
            *(uint32_t*)(smem + SM_XH + off1) = h;
            *(uint32_t*)(smem + SM_XL + off1) = l;
        }
    __syncthreads();     // T complete (both M-halves) before GEMM2 reads K=64

    #pragma unroll
    for (int mt = 0; mt < 2; mt++)
        #pragma unroll
        for (int nt = 0; nt < 4; nt++)
            #pragma unroll
            for (int q = 0; q < 4; q++) acc[mt][nt][q] = 0.0f;

    // ---- GEMM2: Y = Wproj @ T ----
    gemm32(sb, SM_WPH, SM_WPL, lane, mhalf, pbase, acc);

    // ---- store Y ----
    #pragma unroll
    for (int mt = 0; mt < 2; mt++)
        #pragma unroll
        for (int nt = 0; nt < 4; nt++) {
            const int r0 = mhalf * 32 + mt * 16 + g, r1 = r0 + 8;
            const int pp = pbase + nt * 8 + 2 * t;
            *(float2*)(ob + (size_t)r0 * 65536 + pp) =
                make_float2(acc[mt][nt][0], acc[mt][nt][1]);
            *(float2*)(ob + (size_t)r1 * 65536 + pp) =
                make_float2(acc[mt][nt][2], acc[mt][nt][3]);
        }
}

extern "C" void kernel_launch(void* const* d_in, const int* in_sizes, int n_in,
                              void* d_out, int out_size)
{
    const float* x      = (const float*)d_in[0];
    const float* illu   = (const float*)d_in[1];
    const float* wvspec = (const float*)d_in[4];
    const float* wvspat = (const float*)d_in[7];
    const float* wproj  = (const float*)d_in[10];
    float* out = (float*)d_out;

    cudaFuncSetAttribute(fused_hmma2, cudaFuncAttributeMaxDynamicSharedMemorySize,
                         SM_TOTAL);
    const int n_pix = 4 * 256 * 256;
    fused_hmma2<<<n_pix / TP, TPB, SM_TOTAL>>>(x, illu, wvspec, wvspat, wproj, out);
}

// round 5
// speedup vs baseline: 1.5874x; 1.5874x over previous
#include <cuda_runtime.h>
#include <cuda_bf16.h>
#include <cstdint>

// HyperspectralAttention collapses (per-head dim == 1 => softmax == 1) to
//   out = W_proj @ ( illu * ( (0.6*W_v_spec + 0.4*W_v_spat) @ x ) )
// Two 64 x 262144 x 64 GEMMs on mma.sync bf16 3-way split (fp32 accuracy).
//
// R5: persistent CTAs (grid = #SMs), 512 threads, grid-stride over 2048
// 128-pixel tiles. X double-buffered via cp.async (fp32 staging + smem
// convert), illu prefetched one phase ahead. Weights split once per CTA.

#define TPB 512
#define TP  128
#define NTILES 2048

// smem byte offsets
#define SM_WMH 0u
#define SM_WML 8192u
#define SM_WPH 16384u
#define SM_WPL 24576u
#define SM_XH  32768u      // bf16 hi, swizzled; doubles as T-hi
#define SM_XL  49152u      // bf16 lo, swizzled; doubles as T-lo
#define SM_ST0 65536u      // fp32 X stage 0 (64x128)
#define SM_ST1 98304u      // fp32 X stage 1
#define SM_ILL 131072u     // fp32 illu, 64 x 132 padded
#define ILL_STRIDE 132
#define SM_TOTAL (131072 + 64 * ILL_STRIDE * 4)   // 164864

__device__ __forceinline__ uint32_t smem_u32(const void* p) {
    uint32_t a;
    asm("{ .reg .u64 t; cvta.to.shared.u64 t, %1; cvt.u32.u64 %0, t; }"
        : "=r"(a) : "l"(p));
    return a;
}
__device__ __forceinline__ void cp_async16(uint32_t dst, const void* src) {
    asm volatile("cp.async.cg.shared.global [%0], [%1], 16;"
                 :: "r"(dst), "l"(src) : "memory");
}
__device__ __forceinline__ void cp_commit() {
    asm volatile("cp.async.commit_group;" ::: "memory");
}
template <int N>
__device__ __forceinline__ void cp_wait() {
    asm volatile("cp.async.wait_group %0;" :: "n"(N) : "memory");
}
__device__ __forceinline__ void ldsm4(uint32_t addr, uint32_t r[4]) {
    asm volatile("ldmatrix.sync.aligned.m8n8.x4.shared.b16 {%0,%1,%2,%3}, [%4];"
                 : "=r"(r[0]), "=r"(r[1]), "=r"(r[2]), "=r"(r[3]) : "r"(addr));
}
__device__ __forceinline__ void ldsm4t(uint32_t addr, uint32_t r[4]) {
    asm volatile("ldmatrix.sync.aligned.m8n8.x4.trans.shared.b16 {%0,%1,%2,%3}, [%4];"
                 : "=r"(r[0]), "=r"(r[1]), "=r"(r[2]), "=r"(r[3]) : "r"(addr));
}
__device__ __forceinline__ void mma16816(float c[4], const uint32_t a[4],
                                         uint32_t b0, uint32_t b1) {
    asm volatile("mma.sync.aligned.m16n8k16.row.col.f32.bf16.bf16.f32 "
                 "{%0,%1,%2,%3}, {%4,%5,%6,%7}, {%8,%9}, {%0,%1,%2,%3};"
                 : "+f"(c[0]), "+f"(c[1]), "+f"(c[2]), "+f"(c[3])
                 : "r"(a[0]), "r"(a[1]), "r"(a[2]), "r"(a[3]), "r"(b0), "r"(b1));
}
__device__ __forceinline__ void split2(float v0, float v1, uint32_t& hi, uint32_t& lo) {
    __nv_bfloat16 h0 = __float2bfloat16(v0);
    __nv_bfloat16 h1 = __float2bfloat16(v1);
    __nv_bfloat162 hp, lp;
    hp.x = h0; hp.y = h1;
    lp.x = __float2bfloat16(v0 - __bfloat162float(h0));
    lp.y = __float2bfloat16(v1 - __bfloat162float(h1));
    hi = *reinterpret_cast<uint32_t*>(&hp);
    lo = *reinterpret_cast<uint32_t*>(&lp);
}

// 16x32x64 sub-GEMM for one warp: rows [mbase,+16), pixels [pbase,+32).
__device__ __forceinline__ void gemm16(uint32_t sb, uint32_t whOff, uint32_t wlOff,
                                       int lane, int mbase, int pbase,
                                       float acc[4][4]) {
    const uint32_t arow = (uint32_t)(mbase + ((lane >> 3) & 1) * 8 + (lane & 7));
    const uint32_t asw  = (uint32_t)(lane & 7) << 4;
    #pragma unroll
    for (int kc = 0; kc < 4; kc++) {
        const uint32_t acol = ((uint32_t)(kc * 32 + ((lane >> 4) & 1) * 16)) ^ asw;
        uint32_t ah[4], al[4];
        ldsm4(sb + whOff + arow * 128 + acol, ah);
        ldsm4(sb + wlOff + arow * 128 + acol, al);
        const uint32_t brow = kc * 16 + (lane & 15);
        const uint32_t bsw  = (brow & 7) << 4;
        uint32_t bh[2][4], bl[2][4];
        #pragma unroll
        for (int pr = 0; pr < 2; pr++) {
            const uint32_t ncol = pbase + pr * 16 + ((lane >> 4) & 1) * 8;
            const uint32_t off  = brow * 256 + (((uint32_t)(2 * ncol)) ^ bsw);
            ldsm4t(sb + SM_XH + off, bh[pr]);
            ldsm4t(sb + SM_XL + off, bl[pr]);
        }
        #pragma unroll
        for (int nt = 0; nt < 4; nt++) {
            const uint32_t b0h = bh[nt >> 1][(nt & 1) * 2];
            const uint32_t b1h = bh[nt >> 1][(nt & 1) * 2 + 1];
            const uint32_t b0l = bl[nt >> 1][(nt & 1) * 2];
            const uint32_t b1l = bl[nt >> 1][(nt & 1) * 2 + 1];
            mma16816(acc[nt], ah, b0h, b1h);
            mma16816(acc[nt], ah, b0l, b1l);
            mma16816(acc[nt], al, b0h, b1h);
        }
    }
}

__device__ __forceinline__ void issue_x(const float* x, int t, uint32_t stOff,
                                        uint32_t sb, int tid) {
    const size_t base = (size_t)(t >> 9) * 4194304 + (size_t)((t & 511) * TP);
    const float* xb = x + base;
    #pragma unroll
    for (int i = tid; i < 2048; i += TPB) {
        const int c = i >> 5, p4 = (i & 31) * 4;
        cp_async16(sb + stOff + (uint32_t)(c * 128 + p4) * 4,
                   xb + (size_t)c * 65536 + p4);
    }
}
__device__ __forceinline__ void issue_ill(const float* illu, int t,
                                          uint32_t sb, int tid) {
    const size_t base = (size_t)(t >> 9) * 4194304 + (size_t)((t & 511) * TP);
    const float* ib = illu + base;
    #pragma unroll
    for (int i = tid; i < 2048; i += TPB) {
        const int c = i >> 5, p4 = (i & 31) * 4;
        cp_async16(sb + SM_ILL + (uint32_t)(c * ILL_STRIDE + p4) * 4,
                   ib + (size_t)c * 65536 + p4);
    }
}

__global__ __launch_bounds__(TPB, 1) void fused_pipe(
    const float* __restrict__ x, const float* __restrict__ illu,
    const float* __restrict__ wvspec, const float* __restrict__ wvspat,
    const float* __restrict__ wproj, float* __restrict__ out)
{
    extern __shared__ char smem[];
    const uint32_t sb = smem_u32(smem);
    const int tid = threadIdx.x, lane = tid & 31, w = tid >> 5;
    const int mbase = (w & 3) * 16, pbase = (w >> 2) * 32;
    const int g = lane >> 2, tq = lane & 3;

    // ---- weights (once per CTA) ----
    for (int i = tid; i < 4096; i += TPB) {
        const int o = i >> 6, c = i & 63;
        const uint32_t off = (uint32_t)(o * 128) +
                             (((uint32_t)(2 * c)) ^ ((uint32_t)(o & 7) << 4));
        const float wm = 0.6f * wvspec[i] + 0.4f * wvspat[i];
        __nv_bfloat16 h = __float2bfloat16(wm);
        *(__nv_bfloat16*)(smem + SM_WMH + off) = h;
        *(__nv_bfloat16*)(smem + SM_WML + off) =
            __float2bfloat16(wm - __bfloat162float(h));
        const float wp = wproj[i];
        h = __float2bfloat16(wp);
        *(__nv_bfloat16*)(smem + SM_WPH + off) = h;
        *(__nv_bfloat16*)(smem + SM_WPL + off) =
            __float2bfloat16(wp - __bfloat162float(h));
    }

    int t = blockIdx.x;
    if (t >= NTILES) return;
    const int stride = gridDim.x;

    // prologue: X0 -> stage0, ill0
    issue_x(x, t, SM_ST0, sb, tid); cp_commit();
    issue_ill(illu, t, sb, tid);    cp_commit();

    for (int i = 0; t < NTILES; i++) {
        const int tn = t + stride;
        // prefetch next X into the other stage
        if (tn < NTILES) issue_x(x, tn, (i & 1) ? SM_ST0 : SM_ST1, sb, tid);
        cp_commit();
        cp_wait<2>();            // X_t arrived (in-order groups)
        __syncthreads();

        // ---- convert stage -> XH/XL (bf16 split, swizzled) ----
        {
            const float* ST = (const float*)(smem + ((i & 1) ? SM_ST1 : SM_ST0));
            #pragma unroll
            for (int j = tid; j < 2048; j += TPB) {
                const int c = j >> 5, p = (j & 31) * 4;
                const float4 v = *(const float4*)&ST[c * 128 + p];
                uint32_t h0, l0, h1, l1;
                split2(v.x, v.y, h0, l0);
                split2(v.z, v.w, h1, l1);
                const uint32_t off = (uint32_t)(c * 256) +
                                     (((uint32_t)(2 * p)) ^ ((uint32_t)(c & 7) << 4));
                *(uint2*)(smem + SM_XH + off) = make_uint2(h0, h1);
                *(uint2*)(smem + SM_XL + off) = make_uint2(l0, l1);
            }
        }
        __syncthreads();

        float acc[4][4];
        #pragma unroll
        for (int nt = 0; nt < 4; nt++)
            #pragma unroll
            for (int q = 0; q < 4; q++) acc[nt][q] = 0.0f;

        // ---- GEMM1 ----
        gemm16(sb, SM_WMH, SM_WML, lane, mbase, pbase, acc);

        cp_wait<1>();            // ill_t arrived (X_{t+1} may still fly)
        __syncthreads();         // all warps done reading XH/XL + ill visible

        // ---- epilogue 1: T = ill * D1 -> XH/XL ----
        {
            const float* ILLF = (const float*)(smem + SM_ILL);
            #pragma unroll
            for (int nt = 0; nt < 4; nt++) {
                const int r0 = mbase + g, r1 = r0 + 8;
                const int pp = pbase + nt * 8 + 2 * tq;
                const float2 i0 = *(const float2*)&ILLF[r0 * ILL_STRIDE + pp];
                const float2 i1 = *(const float2*)&ILLF[r1 * ILL_STRIDE + pp];
                uint32_t h, l;
                split2(acc[nt][0] * i0.x, acc[nt][1] * i0.y, h, l);
                const uint32_t off0 = (uint32_t)(r0 * 256) +
                                      (((uint32_t)(2 * pp)) ^ ((uint32_t)(r0 & 7) << 4));
                *(uint32_t*)(smem + SM_XH + off0) = h;
                *(uint32_t*)(smem + SM_XL + off0) = l;
                split2(acc[nt][2] * i1.x, acc[nt][3] * i1.y, h, l);
                const uint32_t off1 = (uint32_t)(r1 * 256) +
                                      (((uint32_t)(2 * pp)) ^ ((uint32_t)(r1 & 7) << 4));
                *(uint32_t*)(smem + SM_XH + off1) = h;
                *(uint32_t*)(smem + SM_XL + off1) = l;
            }
        }
        __syncthreads();         // T complete; ill buffer free

        // prefetch next illu
        if (tn < NTILES) issue_ill(illu, tn, sb, tid);
        cp_commit();

        #pragma unroll
        for (int nt = 0; nt < 4; nt++)
            #pragma unroll
            for (int q = 0; q < 4; q++) acc[nt][q] = 0.0f;

        // ---- GEMM2 ----
        gemm16(sb, SM_WPH, SM_WPL, lane, mbase, pbase, acc);

        // ---- store ----
        {
            float* ob = out + (size_t)(t >> 9) * 4194304 + (size_t)((t & 511) * TP);
            #pragma unroll
            for (int nt = 0; nt < 4; nt++) {
                const int r0 = mbase + g, r1 = r0 + 8;
                const int pp = pbase + nt * 8 + 2 * tq;
                *(float2*)(ob + (size_t)r0 * 65536 + pp) =
                    make_float2(acc[nt][0], acc[nt][1]);
                *(float2*)(ob + (size_t)r1 * 65536 + pp) =
                    make_float2(acc[nt][2], acc[nt][3]);
            }
        }
        t = tn;
        // next iter's convert is fenced by the cp_wait<2> + __syncthreads above
    }
}

extern "C" void kernel_launch(void* const* d_in, const int* in_sizes, int n_in,
                              void* d_out, int out_size)
{
    const float* x      = (const float*)d_in[0];
    const float* illu   = (const float*)d_in[1];
    const float* wvspec = (const float*)d_in[4];
    const float* wvspat = (const float*)d_in[7];
    const float* wproj  = (const float*)d_in[10];
    float* out = (float*)d_out;

    int dev = 0, sms = 148;
    cudaGetDevice(&dev);
    cudaDeviceGetAttribute(&sms, cudaDevAttrMultiProcessorCount, dev);
    if (sms < 1) sms = 148;
    if (sms > NTILES) sms = NTILES;

    cudaFuncSetAttribute(fused_pipe, cudaFuncAttributeMaxDynamicSharedMemorySize,
                         SM_TOTAL);
    fused_pipe<<<sms, TPB, SM_TOTAL>>>(x, illu, wvspec, wvspat, wproj, out);
}

// round 6
// speedup vs baseline: 1.6770x; 1.0564x over previous
#include <cuda_runtime.h>
#include <cuda_bf16.h>
#include <cstdint>

// HyperspectralAttention collapses (per-head dim == 1 => softmax == 1) to
//   out = W_proj @ ( illu * ( (0.6*W_v_spec + 0.4*W_v_spat) @ x ) )
// Two 64 x 262144 x 64 GEMMs on mma.sync bf16 3-way split (fp32 accuracy).
//
// R6: persistent CTAs, 2 CTAs/SM (phase interleaving), 256 threads / 8 fat
// warps (32 rows x 32 px each => 33% less ldmatrix traffic). Next-tile X
// prefetched into REGISTERS (no fp32 smem staging), illu via cp.async.

#define TPB 256
#define TP  128
#define NTILES 2048

// smem byte offsets (per CTA: 99328 B -> 2 CTAs/SM)
#define SM_WMH 0u
#define SM_WML 8192u
#define SM_WPH 16384u
#define SM_WPL 24576u
#define SM_XH  32768u      // bf16 hi, swizzled; doubles as T-hi
#define SM_XL  49152u      // bf16 lo, swizzled; doubles as T-lo
#define SM_ILL 65536u      // fp32 illu, 64 x 132 padded
#define ILL_STRIDE 132
#define SM_TOTAL (65536 + 64 * ILL_STRIDE * 4)

__device__ __forceinline__ uint32_t smem_u32(const void* p) {
    uint32_t a;
    asm("{ .reg .u64 t; cvta.to.shared.u64 t, %1; cvt.u32.u64 %0, t; }"
        : "=r"(a) : "l"(p));
    return a;
}
__device__ __forceinline__ void cp_async16(uint32_t dst, const void* src) {
    asm volatile("cp.async.cg.shared.global [%0], [%1], 16;"
                 :: "r"(dst), "l"(src) : "memory");
}
__device__ __forceinline__ void cp_commit() {
    asm volatile("cp.async.commit_group;" ::: "memory");
}
template <int N>
__device__ __forceinline__ void cp_wait() {
    asm volatile("cp.async.wait_group %0;" :: "n"(N) : "memory");
}
__device__ __forceinline__ void ldg128(float4& v, const float* p) {
    asm volatile("ld.global.nc.v4.f32 {%0,%1,%2,%3}, [%4];"
                 : "=f"(v.x), "=f"(v.y), "=f"(v.z), "=f"(v.w) : "l"(p));
}
__device__ __forceinline__ void ldsm4(uint32_t addr, uint32_t r[4]) {
    asm volatile("ldmatrix.sync.aligned.m8n8.x4.shared.b16 {%0,%1,%2,%3}, [%4];"
                 : "=r"(r[0]), "=r"(r[1]), "=r"(r[2]), "=r"(r[3]) : "r"(addr));
}
__device__ __forceinline__ void ldsm4t(uint32_t addr, uint32_t r[4]) {
    asm volatile("ldmatrix.sync.aligned.m8n8.x4.trans.shared.b16 {%0,%1,%2,%3}, [%4];"
                 : "=r"(r[0]), "=r"(r[1]), "=r"(r[2]), "=r"(r[3]) : "r"(addr));
}
__device__ __forceinline__ void mma16816(float c[4], const uint32_t a[4],
                                         uint32_t b0, uint32_t b1) {
    asm volatile("mma.sync.aligned.m16n8k16.row.col.f32.bf16.bf16.f32 "
                 "{%0,%1,%2,%3}, {%4,%5,%6,%7}, {%8,%9}, {%0,%1,%2,%3};"
                 : "+f"(c[0]), "+f"(c[1]), "+f"(c[2]), "+f"(c[3])
                 : "r"(a[0]), "r"(a[1]), "r"(a[2]), "r"(a[3]), "r"(b0), "r"(b1));
}
__device__ __forceinline__ void split2(float v0, float v1, uint32_t& hi, uint32_t& lo) {
    __nv_bfloat16 h0 = __float2bfloat16(v0);
    __nv_bfloat16 h1 = __float2bfloat16(v1);
    __nv_bfloat162 hp, lp;
    hp.x = h0; hp.y = h1;
    lp.x = __float2bfloat16(v0 - __bfloat162float(h0));
    lp.y = __float2bfloat16(v1 - __bfloat162float(h1));
    hi = *reinterpret_cast<uint32_t*>(&hp);
    lo = *reinterpret_cast<uint32_t*>(&lp);
}

// 32x32x64 sub-GEMM per warp: rows [mhalf*32,+32), pixels [pbase,+32).
__device__ __forceinline__ void gemm32(uint32_t sb, uint32_t whOff, uint32_t wlOff,
                                       int lane, int mhalf, int pbase,
                                       float acc[2][4][4]) {
    const uint32_t arow = ((lane >> 3) & 1) * 8 + (lane & 7);
    const uint32_t asw  = (uint32_t)(lane & 7) << 4;
    const uint32_t mb   = (uint32_t)(mhalf * 32);
    #pragma unroll
    for (int kc = 0; kc < 4; kc++) {
        const uint32_t acol = ((uint32_t)(kc * 32 + ((lane >> 4) & 1) * 16)) ^ asw;
        uint32_t ah[2][4], al[2][4];
        #pragma unroll
        for (int mt = 0; mt < 2; mt++) {
            const uint32_t off = (mb + mt * 16 + arow) * 128 + acol;
            ldsm4(sb + whOff + off, ah[mt]);
            ldsm4(sb + wlOff + off, al[mt]);
        }
        const uint32_t brow = kc * 16 + (lane & 15);
        const uint32_t bsw  = (brow & 7) << 4;
        uint32_t bh[2][4], bl[2][4];
        #pragma unroll
        for (int pr = 0; pr < 2; pr++) {
            const uint32_t ncol = pbase + pr * 16 + ((lane >> 4) & 1) * 8;
            const uint32_t off  = brow * 256 + (((uint32_t)(2 * ncol)) ^ bsw);
            ldsm4t(sb + SM_XH + off, bh[pr]);
            ldsm4t(sb + SM_XL + off, bl[pr]);
        }
        #pragma unroll
        for (int mt = 0; mt < 2; mt++)
            #pragma unroll
            for (int nt = 0; nt < 4; nt++) {
                const uint32_t b0h = bh[nt >> 1][(nt & 1) * 2];
                const uint32_t b1h = bh[nt >> 1][(nt & 1) * 2 + 1];
                const uint32_t b0l = bl[nt >> 1][(nt & 1) * 2];
                const uint32_t b1l = bl[nt >> 1][(nt & 1) * 2 + 1];
                mma16816(acc[mt][nt], ah[mt], b0h, b1h);
                mma16816(acc[mt][nt], ah[mt], b0l, b1l);
                mma16816(acc[mt][nt], al[mt], b0h, b1h);
            }
    }
}

__device__ __forceinline__ size_t tile_base(int t) {
    return (size_t)(t >> 9) * 4194304 + (size_t)((t & 511) * TP);
}
__device__ __forceinline__ void issue_x_regs(const float* x, int t, int tid,
                                             float4 xr[8]) {
    const float* xb = x + tile_base(t);
    #pragma unroll
    for (int k = 0; k < 8; k++) {
        const int i = tid + k * TPB;
        const int c = i >> 5, p4 = (i & 31) * 4;
        ldg128(xr[k], xb + (size_t)c * 65536 + p4);
    }
}
__device__ __forceinline__ void issue_ill(const float* illu, int t, int tid,
                                          uint32_t sb) {
    const float* ib = illu + tile_base(t);
    #pragma unroll
    for (int k = 0; k < 8; k++) {
        const int i = tid + k * TPB;
        const int c = i >> 5, p4 = (i & 31) * 4;
        cp_async16(sb + SM_ILL + (uint32_t)(c * ILL_STRIDE + p4) * 4,
                   ib + (size_t)c * 65536 + p4);
    }
    cp_commit();
}

__global__ __launch_bounds__(TPB, 2) void fused_pipe2(
    const float* __restrict__ x, const float* __restrict__ illu,
    const float* __restrict__ wvspec, const float* __restrict__ wvspat,
    const float* __restrict__ wproj, float* __restrict__ out)
{
    extern __shared__ char smem[];
    const uint32_t sb = smem_u32(smem);
    const int tid = threadIdx.x, lane = tid & 31, w = tid >> 5;
    const int mhalf = w & 1, pbase = (w >> 1) * 32;
    const int g = lane >> 2, tq = lane & 3;

    // ---- weights (once per CTA) ----
    for (int i = tid; i < 4096; i += TPB) {
        const int o = i >> 6, c = i & 63;
        const uint32_t off = (uint32_t)(o * 128) +
                             (((uint32_t)(2 * c)) ^ ((uint32_t)(o & 7) << 4));
        const float wm = 0.6f * wvspec[i] + 0.4f * wvspat[i];
        __nv_bfloat16 h = __float2bfloat16(wm);
        *(__nv_bfloat16*)(smem + SM_WMH + off) = h;
        *(__nv_bfloat16*)(smem + SM_WML + off) =
            __float2bfloat16(wm - __bfloat162float(h));
        const float wp = wproj[i];
        h = __float2bfloat16(wp);
        *(__nv_bfloat16*)(smem + SM_WPH + off) = h;
        *(__nv_bfloat16*)(smem + SM_WPL + off) =
            __float2bfloat16(wp - __bfloat162float(h));
    }

    int t = blockIdx.x;
    if (t >= NTILES) return;
    const int stride = gridDim.x;

    float4 xr[8];
    issue_x_regs(x, t, tid, xr);      // X(t0) -> registers
    issue_ill(illu, t, tid, sb);      // illu(t0) -> smem (async)
    __syncthreads();                  // weights visible

    while (t < NTILES) {
        const int tn = t + stride;

        // ---- split X regs -> XH/XL (swizzled bf16 hi/lo) ----
        #pragma unroll
        for (int k = 0; k < 8; k++) {
            const int i = tid + k * TPB;
            const int c = i >> 5, p = (i & 31) * 4;
            uint32_t h0, l0, h1, l1;
            split2(xr[k].x, xr[k].y, h0, l0);
            split2(xr[k].z, xr[k].w, h1, l1);
            const uint32_t off = (uint32_t)(c * 256) +
                                 (((uint32_t)(2 * p)) ^ ((uint32_t)(c & 7) << 4));
            *(uint2*)(smem + SM_XH + off) = make_uint2(h0, h1);
            *(uint2*)(smem + SM_XL + off) = make_uint2(l0, l1);
        }
        __syncthreads();              // X(t) ready in smem

        float acc[2][4][4];
        #pragma unroll
        for (int mt = 0; mt < 2; mt++)
            #pragma unroll
            for (int nt = 0; nt < 4; nt++)
                #pragma unroll
                for (int q = 0; q < 4; q++) acc[mt][nt][q] = 0.0f;

        // ---- GEMM1: D1 = Wmix @ X ----
        gemm32(sb, SM_WMH, SM_WML, lane, mhalf, pbase, acc);

        // prefetch next X into registers (lands during gemm2 / next split)
        if (tn < NTILES) issue_x_regs(x, tn, tid, xr);

        cp_wait<0>();                 // illu(t) arrived
        __syncthreads();              // gemm1 reads done; illu visible

        // ---- epilogue 1: T = illu * D1 -> XH/XL ----
        {
            const float* ILLF = (const float*)(smem + SM_ILL);
            #pragma unroll
            for (int mt = 0; mt < 2; mt++)
                #pragma unroll
                for (int nt = 0; nt < 4; nt++) {
                    const int r0 = mhalf * 32 + mt * 16 + g, r1 = r0 + 8;
                    const int pp = pbase + nt * 8 + 2 * tq;
                    const float2 i0 = *(const float2*)&ILLF[r0 * ILL_STRIDE + pp];
                    const float2 i1 = *(const float2*)&ILLF[r1 * ILL_STRIDE + pp];
                    uint32_t h, l;
                    split2(acc[mt][nt][0] * i0.x, acc[mt][nt][1] * i0.y, h, l);
                    const uint32_t off0 = (uint32_t)(r0 * 256) +
                                          (((uint32_t)(2 * pp)) ^ ((uint32_t)(r0 & 7) << 4));
                    *(uint32_t*)(smem + SM_XH + off0) = h;
                    *(uint32_t*)(smem + SM_XL + off0) = l;
                    split2(acc[mt][nt][2] * i1.x, acc[mt][nt][3] * i1.y, h, l);
                    const uint32_t off1 = (uint32_t)(r1 * 256) +
                                          (((uint32_t)(2 * pp)) ^ ((uint32_t)(r1 & 7) << 4));
                    *(uint32_t*)(smem + SM_XH + off1) = h;
                    *(uint32_t*)(smem + SM_XL + off1) = l;
                }
        }
        __syncthreads();              // T complete; illu buffer free

        if (tn < NTILES) issue_ill(illu, tn, tid, sb);

        #pragma unroll
        for (int mt = 0; mt < 2; mt++)
            #pragma unroll
            for (int nt = 0; nt < 4; nt++)
                #pragma unroll
                for (int q = 0; q < 4; q++) acc[mt][nt][q] = 0.0f;

        // ---- GEMM2: Y = Wproj @ T ----
        gemm32(sb, SM_WPH, SM_WPL, lane, mhalf, pbase, acc);

        // ---- store ----
        {
            float* ob = out + tile_base(t);
            #pragma unroll
            for (int mt = 0; mt < 2; mt++)
                #pragma unroll
                for (int nt = 0; nt < 4; nt++) {
                    const int r0 = mhalf * 32 + mt * 16 + g, r1 = r0 + 8;
                    const int pp = pbase + nt * 8 + 2 * tq;
                    *(float2*)(ob + (size_t)r0 * 65536 + pp) =
                        make_float2(acc[mt][nt][0], acc[mt][nt][1]);
                    *(float2*)(ob + (size_t)r1 * 65536 + pp) =
                        make_float2(acc[mt][nt][2], acc[mt][nt][3]);
                }
        }
        t = tn;
        __syncthreads();              // gemm2 reads done before next split
    }
}

extern "C" void kernel_launch(void* const* d_in, const int* in_sizes, int n_in,
                              void* d_out, int out_size)
{
    const float* x      = (const float*)d_in[0];
    const float* illu   = (const float*)d_in[1];
    const float* wvspec = (const float*)d_in[4];
    const float* wvspat = (const float*)d_in[7];
    const float* wproj  = (const float*)d_in[10];
    float* out = (float*)d_out;

    int dev = 0, sms = 148;
    cudaGetDevice(&dev);
    cudaDeviceGetAttribute(&sms, cudaDevAttrMultiProcessorCount, dev);
    if (sms < 1) sms = 148;
    int grid = 2 * sms;
    if (grid > NTILES) grid = NTILES;

    cudaFuncSetAttribute(fused_pipe2, cudaFuncAttributeMaxDynamicSharedMemorySize,
                         SM_TOTAL);
    fused_pipe2<<<grid, TPB, SM_TOTAL>>>(x, illu, wvspec, wvspat, wproj, out);
}

// round 7
// speedup vs baseline: 1.9403x; 1.1570x over previous
#include <cuda_runtime.h>
#include <cuda_fp16.h>
#include <cstdint>

// HyperspectralAttention collapses (per-head dim == 1 => softmax == 1) to
//   out = W_proj @ ( illu * ( (0.6*W_v_spec + 0.4*W_v_spat) @ x ) )
// Two 64 x 262144 x 64 GEMMs on mma.sync.
//
// R7: fp16 2-term split. W = single fp16 (rel err ~2^-11, norm-averaged
// ~3e-4 << 1e-3 gate). X/T = fp16 hi + fp16 lo (~22 bits, error negligible).
// => 2 MMAs per step instead of 3 (-33% tensor), A-ldmatrix traffic halved.
// Persistent CTAs, 2/SM, 8 fat warps (32 rows x 32 px), X prefetch in regs,
// illu via cp.async.

#define TPB 256
#define TP  128
#define NTILES 2048

// smem byte offsets (per CTA: 82944 B -> 2 CTAs/SM)
#define SM_WM  0u          // fp16 Wmix, 64 rows x 128B, swizzled
#define SM_WP  8192u       // fp16 Wproj
#define SM_XH  16384u      // fp16 hi, swizzled; doubles as T-hi
#define SM_XL  32768u      // fp16 lo, swizzled; doubles as T-lo
#define SM_ILL 49152u      // fp32 illu, 64 x 132 padded
#define ILL_STRIDE 132
#define SM_TOTAL (49152 + 64 * ILL_STRIDE * 4)

__device__ __forceinline__ uint32_t smem_u32(const void* p) {
    uint32_t a;
    asm("{ .reg .u64 t; cvta.to.shared.u64 t, %1; cvt.u32.u64 %0, t; }"
        : "=r"(a) : "l"(p));
    return a;
}
__device__ __forceinline__ void cp_async16(uint32_t dst, const void* src) {
    asm volatile("cp.async.cg.shared.global [%0], [%1], 16;"
                 :: "r"(dst), "l"(src) : "memory");
}
__device__ __forceinline__ void cp_commit() {
    asm volatile("cp.async.commit_group;" ::: "memory");
}
template <int N>
__device__ __forceinline__ void cp_wait() {
    asm volatile("cp.async.wait_group %0;" :: "n"(N) : "memory");
}
__device__ __forceinline__ void ldg128(float4& v, const float* p) {
    asm volatile("ld.global.nc.v4.f32 {%0,%1,%2,%3}, [%4];"
                 : "=f"(v.x), "=f"(v.y), "=f"(v.z), "=f"(v.w) : "l"(p));
}
__device__ __forceinline__ void ldsm4(uint32_t addr, uint32_t r[4]) {
    asm volatile("ldmatrix.sync.aligned.m8n8.x4.shared.b16 {%0,%1,%2,%3}, [%4];"
                 : "=r"(r[0]), "=r"(r[1]), "=r"(r[2]), "=r"(r[3]) : "r"(addr));
}
__device__ __forceinline__ void ldsm4t(uint32_t addr, uint32_t r[4]) {
    asm volatile("ldmatrix.sync.aligned.m8n8.x4.trans.shared.b16 {%0,%1,%2,%3}, [%4];"
                 : "=r"(r[0]), "=r"(r[1]), "=r"(r[2]), "=r"(r[3]) : "r"(addr));
}
__device__ __forceinline__ void mma16816(float c[4], const uint32_t a[4],
                                         uint32_t b0, uint32_t b1) {
    asm volatile("mma.sync.aligned.m16n8k16.row.col.f32.f16.f16.f32 "
                 "{%0,%1,%2,%3}, {%4,%5,%6,%7}, {%8,%9}, {%0,%1,%2,%3};"
                 : "+f"(c[0]), "+f"(c[1]), "+f"(c[2]), "+f"(c[3])
                 : "r"(a[0]), "r"(a[1]), "r"(a[2]), "r"(a[3]), "r"(b0), "r"(b1));
}
// split (v0,v1) into fp16 hi pair + fp16 residual pair
__device__ __forceinline__ void split2h(float v0, float v1, uint32_t& hi, uint32_t& lo) {
    __half2 hp = __floats2half2_rn(v0, v1);
    const float r0 = v0 - __half2float(__low2half(hp));
    const float r1 = v1 - __half2float(__high2half(hp));
    __half2 lp = __floats2half2_rn(r0, r1);
    hi = *reinterpret_cast<uint32_t*>(&hp);
    lo = *reinterpret_cast<uint32_t*>(&lp);
}

// 32x32x64 sub-GEMM per warp: rows [mhalf*32,+32), pixels [pbase,+32).
// 2-term: acc += W * Xh + W * Xl.
__device__ __forceinline__ void gemm32(uint32_t sb, uint32_t wOff,
                                       int lane, int mhalf, int pbase,
                                       float acc[2][4][4]) {
    const uint32_t arow = ((lane >> 3) & 1) * 8 + (lane & 7);
    const uint32_t asw  = (uint32_t)(lane & 7) << 4;
    const uint32_t mb   = (uint32_t)(mhalf * 32);
    #pragma unroll
    for (int kc = 0; kc < 4; kc++) {
        const uint32_t acol = ((uint32_t)(kc * 32 + ((lane >> 4) & 1) * 16)) ^ asw;
        uint32_t aw[2][4];
        #pragma unroll
        for (int mt = 0; mt < 2; mt++)
            ldsm4(sb + wOff + (mb + mt * 16 + arow) * 128 + acol, aw[mt]);
        const uint32_t brow = kc * 16 + (lane & 15);
        const uint32_t bsw  = (brow & 7) << 4;
        uint32_t bh[2][4], bl[2][4];
        #pragma unroll
        for (int pr = 0; pr < 2; pr++) {
            const uint32_t ncol = pbase + pr * 16 + ((lane >> 4) & 1) * 8;
            const uint32_t off  = brow * 256 + (((uint32_t)(2 * ncol)) ^ bsw);
            ldsm4t(sb + SM_XH + off, bh[pr]);
            ldsm4t(sb + SM_XL + off, bl[pr]);
        }
        #pragma unroll
        for (int mt = 0; mt < 2; mt++)
            #pragma unroll
            for (int nt = 0; nt < 4; nt++) {
                const uint32_t b0h = bh[nt >> 1][(nt & 1) * 2];
                const uint32_t b1h = bh[nt >> 1][(nt & 1) * 2 + 1];
                const uint32_t b0l = bl[nt >> 1][(nt & 1) * 2];
                const uint32_t b1l = bl[nt >> 1][(nt & 1) * 2 + 1];
                mma16816(acc[mt][nt], aw[mt], b0h, b1h);
                mma16816(acc[mt][nt], aw[mt], b0l, b1l);
            }
    }
}

__device__ __forceinline__ size_t tile_base(int t) {
    return (size_t)(t >> 9) * 4194304 + (size_t)((t & 511) * TP);
}
__device__ __forceinline__ void issue_x_regs(const float* x, int t, int tid,
                                             float4 xr[8]) {
    const float* xb = x + tile_base(t);
    #pragma unroll
    for (int k = 0; k < 8; k++) {
        const int i = tid + k * TPB;
        const int c = i >> 5, p4 = (i & 31) * 4;
        ldg128(xr[k], xb + (size_t)c * 65536 + p4);
    }
}
__device__ __forceinline__ void issue_ill(const float* illu, int t, int tid,
                                          uint32_t sb) {
    const float* ib = illu + tile_base(t);
    #pragma unroll
    for (int k = 0; k < 8; k++) {
        const int i = tid + k * TPB;
        const int c = i >> 5, p4 = (i & 31) * 4;
        cp_async16(sb + SM_ILL + (uint32_t)(c * ILL_STRIDE + p4) * 4,
                   ib + (size_t)c * 65536 + p4);
    }
    cp_commit();
}

__global__ __launch_bounds__(TPB, 2) void fused_fp16(
    const float* __restrict__ x, const float* __restrict__ illu,
    const float* __restrict__ wvspec, const float* __restrict__ wvspat,
    const float* __restrict__ wproj, float* __restrict__ out)
{
    extern __shared__ char smem[];
    const uint32_t sb = smem_u32(smem);
    const int tid = threadIdx.x, lane = tid & 31, w = tid >> 5;
    const int mhalf = w & 1, pbase = (w >> 1) * 32;
    const int g = lane >> 2, tq = lane & 3;

    // ---- weights (once per CTA), single fp16 ----
    for (int i = tid; i < 4096; i += TPB) {
        const int o = i >> 6, c = i & 63;
        const uint32_t off = (uint32_t)(o * 128) +
                             (((uint32_t)(2 * c)) ^ ((uint32_t)(o & 7) << 4));
        *(__half*)(smem + SM_WM + off) =
            __float2half_rn(0.6f * wvspec[i] + 0.4f * wvspat[i]);
        *(__half*)(smem + SM_WP + off) = __float2half_rn(wproj[i]);
    }

    int t = blockIdx.x;
    if (t >= NTILES) return;
    const int stride = gridDim.x;

    float4 xr[8];
    issue_x_regs(x, t, tid, xr);      // X(t0) -> registers
    issue_ill(illu, t, tid, sb);      // illu(t0) -> smem (async)
    __syncthreads();                  // weights visible

    while (t < NTILES) {
        const int tn = t + stride;

        // ---- split X regs -> XH/XL (swizzled fp16 hi/lo) ----
        #pragma unroll
        for (int k = 0; k < 8; k++) {
            const int i = tid + k * TPB;
            const int c = i >> 5, p = (i & 31) * 4;
            uint32_t h0, l0, h1, l1;
            split2h(xr[k].x, xr[k].y, h0, l0);
            split2h(xr[k].z, xr[k].w, h1, l1);
            const uint32_t off = (uint32_t)(c * 256) +
                                 (((uint32_t)(2 * p)) ^ ((uint32_t)(c & 7) << 4));
            *(uint2*)(smem + SM_XH + off) = make_uint2(h0, h1);
            *(uint2*)(smem + SM_XL + off) = make_uint2(l0, l1);
        }
        __syncthreads();              // X(t) ready in smem

        float acc[2][4][4];
        #pragma unroll
        for (int mt = 0; mt < 2; mt++)
            #pragma unroll
            for (int nt = 0; nt < 4; nt++)
                #pragma unroll
                for (int q = 0; q < 4; q++) acc[mt][nt][q] = 0.0f;

        // ---- GEMM1: D1 = Wmix @ X ----
        gemm32(sb, SM_WM, lane, mhalf, pbase, acc);

        // prefetch next X into registers (lands during gemm2 / next split)
        if (tn < NTILES) issue_x_regs(x, tn, tid, xr);

        cp_wait<0>();                 // illu(t) arrived
        __syncthreads();              // gemm1 reads done; illu visible

        // ---- epilogue 1: T = illu * D1 -> XH/XL ----
        {
            const float* ILLF = (const float*)(smem + SM_ILL);
            #pragma unroll
            for (int mt = 0; mt < 2; mt++)
                #pragma unroll
                for (int nt = 0; nt < 4; nt++) {
                    const int r0 = mhalf * 32 + mt * 16 + g, r1 = r0 + 8;
                    const int pp = pbase + nt * 8 + 2 * tq;
                    const float2 i0 = *(const float2*)&ILLF[r0 * ILL_STRIDE + pp];
                    const float2 i1 = *(const float2*)&ILLF[r1 * ILL_STRIDE + pp];
                    uint32_t h, l;
                    split2h(acc[mt][nt][0] * i0.x, acc[mt][nt][1] * i0.y, h, l);
                    const uint32_t off0 = (uint32_t)(r0 * 256) +
                                          (((uint32_t)(2 * pp)) ^ ((uint32_t)(r0 & 7) << 4));
                    *(uint32_t*)(smem + SM_XH + off0) = h;
                    *(uint32_t*)(smem + SM_XL + off0) = l;
                    split2h(acc[mt][nt][2] * i1.x, acc[mt][nt][3] * i1.y, h, l);
                    const uint32_t off1 = (uint32_t)(r1 * 256) +
                                          (((uint32_t)(2 * pp)) ^ ((uint32_t)(r1 & 7) << 4));
                    *(uint32_t*)(smem + SM_XH + off1) = h;
                    *(uint32_t*)(smem + SM_XL + off1) = l;
                }
        }
        __syncthreads();              // T complete; illu buffer free

        if (tn < NTILES) issue_ill(illu, tn, tid, sb);

        #pragma unroll
        for (int mt = 0; mt < 2; mt++)
            #pragma unroll
            for (int nt = 0; nt < 4; nt++)
                #pragma unroll
                for (int q = 0; q < 4; q++) acc[mt][nt][q] = 0.0f;

        // ---- GEMM2: Y = Wproj @ T ----
        gemm32(sb, SM_WP, lane, mhalf, pbase, acc);

        // ---- store ----
        {
            float* ob = out + tile_base(t);
            #pragma unroll
            for (int mt = 0; mt < 2; mt++)
                #pragma unroll
                for (int nt = 0; nt < 4; nt++) {
                    const int r0 = mhalf * 32 + mt * 16 + g, r1 = r0 + 8;
                    const int pp = pbase + nt * 8 + 2 * tq;
                    *(float2*)(ob + (size_t)r0 * 65536 + pp) =
                        make_float2(acc[mt][nt][0], acc[mt][nt][1]);
                    *(float2*)(ob + (size_t)r1 * 65536 + pp) =
                        make_float2(acc[mt][nt][2], acc[mt][nt][3]);
                }
        }
        t = tn;
        __syncthreads();              // gemm2 reads done before next split
    }
}

extern "C" void kernel_launch(void* const* d_in, const int* in_sizes, int n_in,
                              void* d_out, int out_size)
{
    const float* x      = (const float*)d_in[0];
    const float* illu   = (const float*)d_in[1];
    const float* wvspec = (const float*)d_in[4];
    const float* wvspat = (const float*)d_in[7];
    const float* wproj  = (const float*)d_in[10];
    float* out = (float*)d_out;

    int dev = 0, sms = 148;
    cudaGetDevice(&dev);
    cudaDeviceGetAttribute(&sms, cudaDevAttrMultiProcessorCount, dev);
    if (sms < 1) sms = 148;
    int grid = 2 * sms;
    if (grid > NTILES) grid = NTILES;

    cudaFuncSetAttribute(fused_fp16, cudaFuncAttributeMaxDynamicSharedMemorySize,
                         SM_TOTAL);
    fused_fp16<<<grid, TPB, SM_TOTAL>>>(x, illu, wvspec, wvspat, wproj, out);
}

// round 8
// speedup vs baseline: 1.9669x; 1.0137x over previous
#include <cuda_runtime.h>
#include <cuda_fp16.h>
#include <cstdint>

// HyperspectralAttention collapses (per-head dim == 1 => softmax == 1) to
//   out = W_proj @ ( illu * ( (0.6*W_v_spec + 0.4*W_v_spat) @ x ) )
// Two 64 x 262144 x 64 GEMMs on mma.sync, fp16 2-term split
// (W fp16, X/T fp16 hi+lo => err ~3e-4 << 1e-3).
//
// R8: each 256-thread CTA = TWO independent 128-thread warpgroups, each
// owning a 64-pixel tile with private XH/XL/illu smem and a private named
// barrier. 4 independent phase-pipelines per SM (2 CTAs x 2 groups) fill
// each other's barrier/convert gaps. Weights CTA-shared.

#define TPB 256
#define NT  4096            // tiles of 64 px

// smem layout (per CTA: 16384 + 2*33792 = 83968 B -> 2 CTAs/SM)
#define SM_WM   0u          // fp16 Wmix, 64 rows x 128B, swizzled
#define SM_WP   8192u
#define SM_GRP  16384u      // per-group block: XH(8K) XL(8K) ILL(17408)
#define GRP_SZ  33792u
#define G_XH    0u
#define G_XL    8192u
#define G_ILL   16384u
#define ILL_STRIDE 68       // floats per illu row (64 + 4 pad)
#define SM_TOTAL (16384 + 2 * 33792)

__device__ __forceinline__ uint32_t smem_u32(const void* p) {
    uint32_t a;
    asm("{ .reg .u64 t; cvta.to.shared.u64 t, %1; cvt.u32.u64 %0, t; }"
        : "=r"(a) : "l"(p));
    return a;
}
__device__ __forceinline__ void cp_async16(uint32_t dst, const void* src) {
    asm volatile("cp.async.cg.shared.global [%0], [%1], 16;"
                 :: "r"(dst), "l"(src) : "memory");
}
__device__ __forceinline__ void cp_commit() {
    asm volatile("cp.async.commit_group;" ::: "memory");
}
template <int N>
__device__ __forceinline__ void cp_wait() {
    asm volatile("cp.async.wait_group %0;" :: "n"(N) : "memory");
}
__device__ __forceinline__ void gbar(int id) {
    asm volatile("bar.sync %0, 128;" :: "r"(id) : "memory");
}
__device__ __forceinline__ void ldg128(float4& v, const float* p) {
    asm volatile("ld.global.nc.v4.f32 {%0,%1,%2,%3}, [%4];"
                 : "=f"(v.x), "=f"(v.y), "=f"(v.z), "=f"(v.w) : "l"(p));
}
__device__ __forceinline__ void ldsm4(uint32_t addr, uint32_t r[4]) {
    asm volatile("ldmatrix.sync.aligned.m8n8.x4.shared.b16 {%0,%1,%2,%3}, [%4];"
                 : "=r"(r[0]), "=r"(r[1]), "=r"(r[2]), "=r"(r[3]) : "r"(addr));
}
__device__ __forceinline__ void ldsm4t(uint32_t addr, uint32_t r[4]) {
    asm volatile("ldmatrix.sync.aligned.m8n8.x4.trans.shared.b16 {%0,%1,%2,%3}, [%4];"
                 : "=r"(r[0]), "=r"(r[1]), "=r"(r[2]), "=r"(r[3]) : "r"(addr));
}
__device__ __forceinline__ void mma16816(float c[4], const uint32_t a[4],
                                         uint32_t b0, uint32_t b1) {
    asm volatile("mma.sync.aligned.m16n8k16.row.col.f32.f16.f16.f32 "
                 "{%0,%1,%2,%3}, {%4,%5,%6,%7}, {%8,%9}, {%0,%1,%2,%3};"
                 : "+f"(c[0]), "+f"(c[1]), "+f"(c[2]), "+f"(c[3])
                 : "r"(a[0]), "r"(a[1]), "r"(a[2]), "r"(a[3]), "r"(b0), "r"(b1));
}
__device__ __forceinline__ void split2h(float v0, float v1, uint32_t& hi, uint32_t& lo) {
    __half2 hp = __floats2half2_rn(v0, v1);
    const float r0 = v0 - __half2float(__low2half(hp));
    const float r1 = v1 - __half2float(__high2half(hp));
    __half2 lp = __floats2half2_rn(r0, r1);
    hi = *reinterpret_cast<uint32_t*>(&hp);
    lo = *reinterpret_cast<uint32_t*>(&lp);
}

// 32x32x64 sub-GEMM per warp: rows [mhalf*32,+32), px [pbase,+32).
// B tile rows are 128B (64 fp16). 2-term: acc += W*Xh + W*Xl.
__device__ __forceinline__ void gemm32(uint32_t sbW, uint32_t sbXH, uint32_t sbXL,
                                       int lane, int mhalf, int pbase,
                                       float acc[2][4][4]) {
    const uint32_t arow = ((lane >> 3) & 1) * 8 + (lane & 7);
    const uint32_t asw  = (uint32_t)(lane & 7) << 4;
    const uint32_t mb   = (uint32_t)(mhalf * 32);
    #pragma unroll
    for (int kc = 0; kc < 4; kc++) {
        const uint32_t acol = ((uint32_t)(kc * 32 + ((lane >> 4) & 1) * 16)) ^ asw;
        uint32_t aw[2][4];
        #pragma unroll
        for (int mt = 0; mt < 2; mt++)
            ldsm4(sbW + (mb + mt * 16 + arow) * 128 + acol, aw[mt]);
        const uint32_t brow = kc * 16 + (lane & 15);
        const uint32_t bsw  = (brow & 7) << 4;
        uint32_t bh[2][4], bl[2][4];
        #pragma unroll
        for (int pr = 0; pr < 2; pr++) {
            const uint32_t ncol = pbase + pr * 16 + ((lane >> 4) & 1) * 8;
            const uint32_t off  = brow * 128 + (((uint32_t)(2 * ncol)) ^ bsw);
            ldsm4t(sbXH + off, bh[pr]);
            ldsm4t(sbXL + off, bl[pr]);
        }
        #pragma unroll
        for (int mt = 0; mt < 2; mt++)
            #pragma unroll
            for (int nt = 0; nt < 4; nt++) {
                const uint32_t b0h = bh[nt >> 1][(nt & 1) * 2];
                const uint32_t b1h = bh[nt >> 1][(nt & 1) * 2 + 1];
                const uint32_t b0l = bl[nt >> 1][(nt & 1) * 2];
                const uint32_t b1l = bl[nt >> 1][(nt & 1) * 2 + 1];
                mma16816(acc[mt][nt], aw[mt], b0h, b1h);
                mma16816(acc[mt][nt], aw[mt], b0l, b1l);
            }
    }
}

__device__ __forceinline__ size_t tile_base(int t) {
    // 1024 tiles of 64 px per image; image stride 64*65536
    return (size_t)(t >> 10) * 4194304 + (size_t)((t & 1023) * 64);
}
// 64 rows x 64 px fp32 -> 8 float4 per thread (128 threads)
__device__ __forceinline__ void issue_x_regs(const float* x, int t, int gtid,
                                             float4 xr[8]) {
    const float* xb = x + tile_base(t);
    #pragma unroll
    for (int k = 0; k < 8; k++) {
        const int i = gtid + k * 128;
        const int c = i >> 4, p4 = (i & 15) * 4;
        ldg128(xr[k], xb + (size_t)c * 65536 + p4);
    }
}
__device__ __forceinline__ void issue_ill(const float* illu, int t, int gtid,
                                          uint32_t sbIll) {
    const float* ib = illu + tile_base(t);
    #pragma unroll
    for (int k = 0; k < 8; k++) {
        const int i = gtid + k * 128;
        const int c = i >> 4, p4 = (i & 15) * 4;
        cp_async16(sbIll + (uint32_t)(c * ILL_STRIDE + p4) * 4,
                   ib + (size_t)c * 65536 + p4);
    }
    cp_commit();
}

__global__ __launch_bounds__(TPB, 2) void fused_wg(
    const float* __restrict__ x, const float* __restrict__ illu,
    const float* __restrict__ wvspec, const float* __restrict__ wvspat,
    const float* __restrict__ wproj, float* __restrict__ out)
{
    extern __shared__ char smem[];
    const uint32_t sb = smem_u32(smem);
    const int tid  = threadIdx.x;
    const int grp  = tid >> 7;            // 0 / 1
    const int gtid = tid & 127;
    const int lane = tid & 31, w4 = gtid >> 5;
    const int mhalf = w4 & 1, pbase = (w4 >> 1) * 32;
    const int g = lane >> 2, tq = lane & 3;
    const int barid = grp + 1;

    const uint32_t sbG   = sb + SM_GRP + (uint32_t)grp * GRP_SZ;
    const uint32_t sbXH  = sbG + G_XH;
    const uint32_t sbXL  = sbG + G_XL;
    const uint32_t sbILL = sbG + G_ILL;
    const float* ILLF = (const float*)(smem + SM_GRP + (uint32_t)grp * GRP_SZ + G_ILL);

    // ---- weights (once per CTA), single fp16, swizzled 128B rows ----
    for (int i = tid; i < 4096; i += TPB) {
        const int o = i >> 6, c = i & 63;
        const uint32_t off = (uint32_t)(o * 128) +
                             (((uint32_t)(2 * c)) ^ ((uint32_t)(o & 7) << 4));
        *(__half*)(smem + SM_WM + off) =
            __float2half_rn(0.6f * wvspec[i] + 0.4f * wvspat[i]);
        *(__half*)(smem + SM_WP + off) = __float2half_rn(wproj[i]);
    }

    int t = blockIdx.x * 2 + grp;
    const int stride = gridDim.x * 2;

    float4 xr[8];
    if (t < NT) {
        issue_x_regs(x, t, gtid, xr);
        issue_ill(illu, t, gtid, sbILL);
    }
    __syncthreads();                      // weights visible to both groups

    while (t < NT) {
        const int tn = t + stride;

        // ---- split X regs -> XH/XL (swizzled fp16 hi/lo, 128B rows) ----
        #pragma unroll
        for (int k = 0; k < 8; k++) {
            const int i = gtid + k * 128;
            const int c = i >> 4, p = (i & 15) * 4;
            uint32_t h0, l0, h1, l1;
            split2h(xr[k].x, xr[k].y, h0, l0);
            split2h(xr[k].z, xr[k].w, h1, l1);
            const uint32_t off = (uint32_t)(c * 128) +
                                 (((uint32_t)(2 * p)) ^ ((uint32_t)(c & 7) << 4));
            *(uint2*)(smem + (sbXH - sb) + off) = make_uint2(h0, h1);
            *(uint2*)(smem + (sbXL - sb) + off) = make_uint2(l0, l1);
        }
        gbar(barid);                      // X(t) ready for this group

        float acc[2][4][4];
        #pragma unroll
        for (int mt = 0; mt < 2; mt++)
            #pragma unroll
            for (int nt = 0; nt < 4; nt++)
                #pragma unroll
                for (int q = 0; q < 4; q++) acc[mt][nt][q] = 0.0f;

        // ---- GEMM1: D1 = Wmix @ X ----
        gemm32(sb + SM_WM, sbXH, sbXL, lane, mhalf, pbase, acc);

        if (tn < NT) issue_x_regs(x, tn, gtid, xr);   // lands ~1 tile later

        cp_wait<0>();                     // this thread's illu(t) arrived
        gbar(barid);                      // group done reading X; illu visible

        // ---- epilogue 1: T = illu * D1 -> XH/XL ----
        #pragma unroll
        for (int mt = 0; mt < 2; mt++)
            #pragma unroll
            for (int nt = 0; nt < 4; nt++) {
                const int r0 = mhalf * 32 + mt * 16 + g, r1 = r0 + 8;
                const int pp = pbase + nt * 8 + 2 * tq;
                const float2 i0 = *(const float2*)&ILLF[r0 * ILL_STRIDE + pp];
                const float2 i1 = *(const float2*)&ILLF[r1 * ILL_STRIDE + pp];
                uint32_t h, l;
                split2h(acc[mt][nt][0] * i0.x, acc[mt][nt][1] * i0.y, h, l);
                const uint32_t off0 = (uint32_t)(r0 * 128) +
                                      (((uint32_t)(2 * pp)) ^ ((uint32_t)(r0 & 7) << 4));
                *(uint32_t*)(smem + (sbXH - sb) + off0) = h;
                *(uint32_t*)(smem + (sbXL - sb) + off0) = l;
                split2h(acc[mt][nt][2] * i1.x, acc[mt][nt][3] * i1.y, h, l);
                const uint32_t off1 = (uint32_t)(r1 * 128) +
                                      (((uint32_t)(2 * pp)) ^ ((uint32_t)(r1 & 7) << 4));
                *(uint32_t*)(smem + (sbXH - sb) + off1) = h;
                *(uint32_t*)(smem + (sbXL - sb) + off1) = l;
            }
        gbar(barid);                      // T complete; illu buffer free

        if (tn < NT) issue_ill(illu, tn, gtid, sbILL);

        #pragma unroll
        for (int mt = 0; mt < 2; mt++)
            #pragma unroll
            for (int nt = 0; nt < 4; nt++)
                #pragma unroll
                for (int q = 0; q < 4; q++) acc[mt][nt][q] = 0.0f;

        // ---- GEMM2: Y = Wproj @ T ----
        gemm32(sb + SM_WP, sbXH, sbXL, lane, mhalf, pbase, acc);

        // ---- store ----
        {
            float* ob = out + tile_base(t);
            #pragma unroll
            for (int mt = 0; mt < 2; mt++)
                #pragma unroll
                for (int nt = 0; nt < 4; nt++) {
                    const int r0 = mhalf * 32 + mt * 16 + g, r1 = r0 + 8;
                    const int pp = pbase + nt * 8 + 2 * tq;
                    *(float2*)(ob + (size_t)r0 * 65536 + pp) =
                        make_float2(acc[mt][nt][0], acc[mt][nt][1]);
                    *(float2*)(ob + (size_t)r1 * 65536 + pp) =
                        make_float2(acc[mt][nt][2], acc[mt][nt][3]);
                }
        }
        t = tn;
        gbar(barid);                      // group done reading T before resplit
    }
}

extern "C" void kernel_launch(void* const* d_in, const int* in_sizes, int n_in,
                              void* d_out, int out_size)
{
    const float* x      = (const float*)d_in[0];
    const float* illu   = (const float*)d_in[1];
    const float* wvspec = (const float*)d_in[4];
    const float* wvspat = (const float*)d_in[7];
    const float* wproj  = (const float*)d_in[10];
    float* out = (float*)d_out;

    int dev = 0, sms = 148;
    cudaGetDevice(&dev);
    cudaDeviceGetAttribute(&sms, cudaDevAttrMultiProcessorCount, dev);
    if (sms < 1) sms = 148;
    int grid = 2 * sms;
    if (grid * 2 > NT) grid = NT / 2;

    cudaFuncSetAttribute(fused_wg, cudaFuncAttributeMaxDynamicSharedMemorySize,
                         SM_TOTAL);
    fused_wg<<<grid, TPB, SM_TOTAL>>>(x, illu, wvspec, wvspat, wproj, out);
}

// round 9
// speedup vs baseline: 2.1077x; 1.0716x over previous
#include <cuda_runtime.h>
#include <cuda_fp16.h>
#include <cstdint>

// HyperspectralAttention collapses (per-head dim == 1 => softmax == 1) to
//   out = W_proj @ ( illu * ( (0.6*W_v_spec + 0.4*W_v_spat) @ x ) )
// Two 64 x 262144 x 64 GEMMs, fp16 2-term split (W fp16; X/T fp16 hi+lo).
//
// R9: fully barrier-free per-warp pipelines. Each warp owns 16 pixels.
// GEMM1: D1^T[px][o], A = X^T built from direct scalar LDGs (no smem X),
// B = W via non-trans ldmatrix. The GEMM1 accumulator fragment IS the
// GEMM2 A-fragment (k=o chunks = acc n-tile pairs), so T never leaves
// registers. illu per-warp via cp.async. Zero bar.sync in the main loop.

#define TPB 256
#define NWT 16384            // 16-px warp tiles

// smem: W 16KB + 8 per-warp illu buffers [64][20]f32 (5120B each)
#define SM_WM  0u
#define SM_WP  8192u
#define SM_ILL 16384u
#define ILL_WSZ 5120u
#define SM_TOTAL (16384 + 8 * 5120)

__device__ __forceinline__ uint32_t smem_u32(const void* p) {
    uint32_t a;
    asm("{ .reg .u64 t; cvta.to.shared.u64 t, %1; cvt.u32.u64 %0, t; }"
        : "=r"(a) : "l"(p));
    return a;
}
__device__ __forceinline__ void cp_async16(uint32_t dst, const void* src) {
    asm volatile("cp.async.cg.shared.global [%0], [%1], 16;"
                 :: "r"(dst), "l"(src) : "memory");
}
__device__ __forceinline__ void cp_commit() {
    asm volatile("cp.async.commit_group;" ::: "memory");
}
template <int N>
__device__ __forceinline__ void cp_wait() {
    asm volatile("cp.async.wait_group %0;" :: "n"(N) : "memory");
}
__device__ __forceinline__ void ldsm4(uint32_t addr, uint32_t r[4]) {
    asm volatile("ldmatrix.sync.aligned.m8n8.x4.shared.b16 {%0,%1,%2,%3}, [%4];"
                 : "=r"(r[0]), "=r"(r[1]), "=r"(r[2]), "=r"(r[3]) : "r"(addr));
}
__device__ __forceinline__ void mma16816(float c[4], const uint32_t a[4],
                                         uint32_t b0, uint32_t b1) {
    asm volatile("mma.sync.aligned.m16n8k16.row.col.f32.f16.f16.f32 "
                 "{%0,%1,%2,%3}, {%4,%5,%6,%7}, {%8,%9}, {%0,%1,%2,%3};"
                 : "+f"(c[0]), "+f"(c[1]), "+f"(c[2]), "+f"(c[3])
                 : "r"(a[0]), "r"(a[1]), "r"(a[2]), "r"(a[3]), "r"(b0), "r"(b1));
}
__device__ __forceinline__ void split2h(float v0, float v1, uint32_t& hi, uint32_t& lo) {
    __half2 hp = __floats2half2_rn(v0, v1);
    const float r0 = v0 - __half2float(__low2half(hp));
    const float r1 = v1 - __half2float(__high2half(hp));
    __half2 lp = __floats2half2_rn(r0, r1);
    hi = *reinterpret_cast<uint32_t*>(&hp);
    lo = *reinterpret_cast<uint32_t*>(&lp);
}
__device__ __forceinline__ float ldgnc(const float* p) {
    float v;
    asm volatile("ld.global.nc.f32 %0, [%1];" : "=f"(v) : "l"(p));
    return v;
}

// B-frag ldmatrix address on W[o][c] (128B swizzled rows):
// matrix0: n rows ntp*16+0..7, k 0-7; m1: same n, k8-15; m2/m3: n+8.
__device__ __forceinline__ uint32_t waddr(uint32_t sbW, int ntp, int kc, int lane) {
    const int o  = ntp * 16 + ((lane >> 4) & 1) * 8 + (lane & 7);
    const int cb = kc * 32 + ((lane >> 3) & 1) * 16;
    return sbW + (uint32_t)(o * 128) + (uint32_t)(cb ^ ((o & 7) << 4));
}

__device__ __forceinline__ size_t tile_base(int t) {
    return (size_t)(t >> 12) * 4194304 + (size_t)(t & 4095) * 16;
}

// load this lane's 8 X scalars for k-chunk kc of tile t
__device__ __forceinline__ void ldx(const float* xb, int kc, int tq, int g, float v[8]) {
    const float* p0 = xb + (size_t)(kc * 16 + 2 * tq) * 65536 + g;
    v[0] = ldgnc(p0);             v[1] = ldgnc(p0 + 65536);
    v[2] = ldgnc(p0 + 8);         v[3] = ldgnc(p0 + 65536 + 8);
    const float* p1 = p0 + (size_t)8 * 65536;
    v[4] = ldgnc(p1);             v[5] = ldgnc(p1 + 65536);
    v[6] = ldgnc(p1 + 8);         v[7] = ldgnc(p1 + 65536 + 8);
}

__global__ __launch_bounds__(TPB, 2) void fused_pw(
    const float* __restrict__ x, const float* __restrict__ illu,
    const float* __restrict__ wvspec, const float* __restrict__ wvspat,
    const float* __restrict__ wproj, float* __restrict__ out)
{
    extern __shared__ char smem[];
    const uint32_t sb = smem_u32(smem);
    const int tid = threadIdx.x, lane = tid & 31, w = tid >> 5;
    const int g = lane >> 2, tq = lane & 3;

    // ---- weights once per CTA (fp16, [o][c] 128B swizzled rows) ----
    for (int i = tid; i < 4096; i += TPB) {
        const int o = i >> 6, c = i & 63;
        const uint32_t off = (uint32_t)(o * 128) +
                             (((uint32_t)(2 * c)) ^ ((uint32_t)(o & 7) << 4));
        *(__half*)(smem + SM_WM + off) =
            __float2half_rn(0.6f * wvspec[i] + 0.4f * wvspat[i]);
        *(__half*)(smem + SM_WP + off) = __float2half_rn(wproj[i]);
    }
    __syncthreads();   // only CTA-wide barrier in the kernel

    const uint32_t sbWM = sb + SM_WM, sbWP = sb + SM_WP;
    const uint32_t sbIL = sb + SM_ILL + (uint32_t)w * ILL_WSZ;
    const float* ILF = (const float*)(smem + SM_ILL + (size_t)w * ILL_WSZ);

    int t = blockIdx.x * 8 + w;
    const int stride = gridDim.x * 8;
    if (t >= NWT) return;

    float xf[4][8];
    {   // prologue: X(t) scalars + illu(t) cp.async
        const float* xb = x + tile_base(t);
        #pragma unroll
        for (int kc = 0; kc < 4; kc++) ldx(xb, kc, tq, g, xf[kc]);
        const float* ib = illu + tile_base(t);
        #pragma unroll
        for (int k = 0; k < 8; k++) {
            const int j = lane + k * 32, c = j >> 2, q = j & 3;
            cp_async16(sbIL + (uint32_t)(c * 80 + q * 16),
                       ib + (size_t)c * 65536 + q * 4);
        }
        cp_commit();
    }

    while (t < NWT) {
        const int tn = t + stride;
        const float* xbn = (tn < NWT) ? x + tile_base(tn) : x;

        // ---- GEMM1: acc1[px16][o64] = X^T @ Wm^T ----
        float acc1[8][4];
        #pragma unroll
        for (int nt = 0; nt < 8; nt++)
            #pragma unroll
            for (int q = 0; q < 4; q++) acc1[nt][q] = 0.0f;

        #pragma unroll
        for (int kc = 0; kc < 4; kc++) {
            uint32_t ah[4], al[4];
            split2h(xf[kc][0], xf[kc][1], ah[0], al[0]);
            split2h(xf[kc][2], xf[kc][3], ah[1], al[1]);
            split2h(xf[kc][4], xf[kc][5], ah[2], al[2]);
            split2h(xf[kc][6], xf[kc][7], ah[3], al[3]);
            #pragma unroll
            for (int ntp = 0; ntp < 4; ntp++) {
                uint32_t b[4];
                ldsm4(waddr(sbWM, ntp, kc, lane), b);
                mma16816(acc1[2 * ntp],     ah, b[0], b[1]);
                mma16816(acc1[2 * ntp],     al, b[0], b[1]);
                mma16816(acc1[2 * ntp + 1], ah, b[2], b[3]);
                mma16816(acc1[2 * ntp + 1], al, b[2], b[3]);
            }
            if (tn < NWT) ldx(xbn, kc, tq, g, xf[kc]);   // prefetch, regs now free
        }

        cp_wait<0>();
        __syncwarp();          // other lanes' illu(t) cp.async visible

        // ---- epilogue (T = illu * D1, in regs) fused with GEMM2 ----
        float acc2[8][4];
        #pragma unroll
        for (int nt = 0; nt < 8; nt++)
            #pragma unroll
            for (int q = 0; q < 4; q++) acc2[nt][q] = 0.0f;

        #pragma unroll
        for (int kc = 0; kc < 4; kc++) {
            const int nA = 2 * kc, nB = 2 * kc + 1;
            const int oa = nA * 8 + 2 * tq, ob_ = nB * 8 + 2 * tq;
            const float u0 = acc1[nA][0] * ILF[oa * 20 + g];
            const float u1 = acc1[nA][1] * ILF[(oa + 1) * 20 + g];
            const float u2 = acc1[nA][2] * ILF[oa * 20 + g + 8];
            const float u3 = acc1[nA][3] * ILF[(oa + 1) * 20 + g + 8];
            const float v0 = acc1[nB][0] * ILF[ob_ * 20 + g];
            const float v1 = acc1[nB][1] * ILF[(ob_ + 1) * 20 + g];
            const float v2 = acc1[nB][2] * ILF[ob_ * 20 + g + 8];
            const float v3 = acc1[nB][3] * ILF[(ob_ + 1) * 20 + g + 8];
            uint32_t ah[4], al[4];
            split2h(u0, u1, ah[0], al[0]);   // (m=g,   k=2tq,2tq+1)
            split2h(u2, u3, ah[1], al[1]);   // (m=g+8, k=2tq,2tq+1)
            split2h(v0, v1, ah[2], al[2]);   // (m=g,   k=2tq+8,+9)
            split2h(v2, v3, ah[3], al[3]);   // (m=g+8, k+8)
            #pragma unroll
            for (int ntp = 0; ntp < 4; ntp++) {
                uint32_t b[4];
                ldsm4(waddr(sbWP, ntp, kc, lane), b);
                mma16816(acc2[2 * ntp],     ah, b[0], b[1]);
                mma16816(acc2[2 * ntp],     al, b[0], b[1]);
                mma16816(acc2[2 * ntp + 1], ah, b[2], b[3]);
                mma16816(acc2[2 * ntp + 1], al, b[2], b[3]);
            }
        }
        __syncwarp();          // all lanes done reading illu(t)

        // prefetch illu(t+1)
        if (tn < NWT) {
            const float* ib = illu + tile_base(tn);
            #pragma unroll
            for (int k = 0; k < 8; k++) {
                const int j = lane + k * 32, c = j >> 2, q = j & 3;
                cp_async16(sbIL + (uint32_t)(c * 80 + q * 16),
                           ib + (size_t)c * 65536 + q * 4);
            }
            cp_commit();
        }

        // ---- store Y^T frags -> out[o'][px] ----
        {
            float* obp = out + tile_base(t);
            #pragma unroll
            for (int nt = 0; nt < 8; nt++) {
                float* q = obp + (size_t)(nt * 8 + 2 * tq) * 65536 + g;
                q[0]         = acc2[nt][0];
                q[65536]     = acc2[nt][1];
                q[8]         = acc2[nt][2];
                q[65536 + 8] = acc2[nt][3];
            }
        }
        t = tn;
    }
}

extern "C" void kernel_launch(void* const* d_in, const int* in_sizes, int n_in,
                              void* d_out, int out_size)
{
    const float* x      = (const float*)d_in[0];
    const float* illu   = (const float*)d_in[1];
    const float* wvspec = (const float*)d_in[4];
    const float* wvspat = (const float*)d_in[7];
    const float* wproj  = (const float*)d_in[10];
    float* out = (float*)d_out;

    int dev = 0, sms = 148;
    cudaGetDevice(&dev);
    cudaDeviceGetAttribute(&sms, cudaDevAttrMultiProcessorCount, dev);
    if (sms < 1) sms = 148;
    int grid = 2 * sms;
    if (grid * 8 > NWT) grid = NWT / 8;

    cudaFuncSetAttribute(fused_pw, cudaFuncAttributeMaxDynamicSharedMemorySize,
                         SM_TOTAL);
    fused_pw<<<grid, TPB, SM_TOTAL>>>(x, illu, wvspec, wvspat, wproj, out);
}

// round 10
// speedup vs baseline: 2.1190x; 1.0054x over previous
#include <cuda_runtime.h>
#include <cuda_fp16.h>
#include <cstdint>

// HyperspectralAttention collapses (per-head dim == 1 => softmax == 1) to
//   out = W_proj @ ( illu * ( (0.6*W_v_spec + 0.4*W_v_spat) @ x ) )
// Two 64 x 262144 x 64 GEMMs on mma.sync, all operands single fp16
// (W, X, T each rounded once; independent roundings => rel_err ~4-5e-4,
// under the 1e-3 gate with ~2x margin).
//
// R10: barrier-free per-warp pipelines (R9 structure), 64 MMAs per 16-px
// warp tile (half of R9). X converts to half2 at load (16 regs of state),
// T = illu * D1 converts in registers, never touches smem. illu per-warp
// via cp.async. Zero bar.sync in the main loop.

#define TPB 256
#define NWT 16384            // 16-px warp tiles

// smem: W 16KB + 8 per-warp illu buffers [64][20]f32 (5120B each)
#define SM_WM  0u
#define SM_WP  8192u
#define SM_ILL 16384u
#define ILL_WSZ 5120u
#define SM_TOTAL (16384 + 8 * 5120)

__device__ __forceinline__ uint32_t smem_u32(const void* p) {
    uint32_t a;
    asm("{ .reg .u64 t; cvta.to.shared.u64 t, %1; cvt.u32.u64 %0, t; }"
        : "=r"(a) : "l"(p));
    return a;
}
__device__ __forceinline__ void cp_async16(uint32_t dst, const void* src) {
    asm volatile("cp.async.cg.shared.global [%0], [%1], 16;"
                 :: "r"(dst), "l"(src) : "memory");
}
__device__ __forceinline__ void cp_commit() {
    asm volatile("cp.async.commit_group;" ::: "memory");
}
template <int N>
__device__ __forceinline__ void cp_wait() {
    asm volatile("cp.async.wait_group %0;" :: "n"(N) : "memory");
}
__device__ __forceinline__ void ldsm4(uint32_t addr, uint32_t r[4]) {
    asm volatile("ldmatrix.sync.aligned.m8n8.x4.shared.b16 {%0,%1,%2,%3}, [%4];"
                 : "=r"(r[0]), "=r"(r[1]), "=r"(r[2]), "=r"(r[3]) : "r"(addr));
}
__device__ __forceinline__ void mma16816(float c[4], const uint32_t a[4],
                                         uint32_t b0, uint32_t b1) {
    asm volatile("mma.sync.aligned.m16n8k16.row.col.f32.f16.f16.f32 "
                 "{%0,%1,%2,%3}, {%4,%5,%6,%7}, {%8,%9}, {%0,%1,%2,%3};"
                 : "+f"(c[0]), "+f"(c[1]), "+f"(c[2]), "+f"(c[3])
                 : "r"(a[0]), "r"(a[1]), "r"(a[2]), "r"(a[3]), "r"(b0), "r"(b1));
}
__device__ __forceinline__ uint32_t packh2(float v0, float v1) {
    __half2 hp = __floats2half2_rn(v0, v1);
    return *reinterpret_cast<uint32_t*>(&hp);
}
__device__ __forceinline__ float ldgnc(const float* p) {
    float v;
    asm volatile("ld.global.nc.f32 %0, [%1];" : "=f"(v) : "l"(p));
    return v;
}

// B-frag ldmatrix address on W[o][c] (128B swizzled rows)
__device__ __forceinline__ uint32_t waddr(uint32_t sbW, int ntp, int kc, int lane) {
    const int o  = ntp * 16 + ((lane >> 4) & 1) * 8 + (lane & 7);
    const int cb = kc * 32 + ((lane >> 3) & 1) * 16;
    return sbW + (uint32_t)(o * 128) + (uint32_t)(cb ^ ((o & 7) << 4));
}

__device__ __forceinline__ size_t tile_base(int t) {
    return (size_t)(t >> 12) * 4194304 + (size_t)(t & 4095) * 16;
}

// load this lane's 8 X scalars for k-chunk kc, convert to A-frag half2 x4
__device__ __forceinline__ void ldxh(const float* xb, int kc, int tq, int g,
                                     uint32_t v[4]) {
    const float* p0 = xb + (size_t)(kc * 16 + 2 * tq) * 65536 + g;
    const float a0 = ldgnc(p0),             a1 = ldgnc(p0 + 65536);
    const float a2 = ldgnc(p0 + 8),         a3 = ldgnc(p0 + 65536 + 8);
    const float* p1 = p0 + (size_t)8 * 65536;
    const float a4 = ldgnc(p1),             a5 = ldgnc(p1 + 65536);
    const float a6 = ldgnc(p1 + 8),         a7 = ldgnc(p1 + 65536 + 8);
    v[0] = packh2(a0, a1);   // (m=g,   k=2tq,2tq+1)
    v[1] = packh2(a2, a3);   // (m=g+8, k=2tq,2tq+1)
    v[2] = packh2(a4, a5);   // (m=g,   k=2tq+8,+9)
    v[3] = packh2(a6, a7);   // (m=g+8, k+8)
}

__global__ __launch_bounds__(TPB, 2) void fused_h1(
    const float* __restrict__ x, const float* __restrict__ illu,
    const float* __restrict__ wvspec, const float* __restrict__ wvspat,
    const float* __restrict__ wproj, float* __restrict__ out)
{
    extern __shared__ char smem[];
    const uint32_t sb = smem_u32(smem);
    const int tid = threadIdx.x, lane = tid & 31, w = tid >> 5;
    const int g = lane >> 2, tq = lane & 3;

    // ---- weights once per CTA (fp16, [o][c] 128B swizzled rows) ----
    for (int i = tid; i < 4096; i += TPB) {
        const int o = i >> 6, c = i & 63;
        const uint32_t off = (uint32_t)(o * 128) +
                             (((uint32_t)(2 * c)) ^ ((uint32_t)(o & 7) << 4));
        *(__half*)(smem + SM_WM + off) =
            __float2half_rn(0.6f * wvspec[i] + 0.4f * wvspat[i]);
        *(__half*)(smem + SM_WP + off) = __float2half_rn(wproj[i]);
    }
    __syncthreads();   // only CTA-wide barrier in the kernel

    const uint32_t sbWM = sb + SM_WM, sbWP = sb + SM_WP;
    const uint32_t sbIL = sb + SM_ILL + (uint32_t)w * ILL_WSZ;
    const float* ILF = (const float*)(smem + SM_ILL + (size_t)w * ILL_WSZ);

    int t = blockIdx.x * 8 + w;
    const int stride = gridDim.x * 8;
    if (t >= NWT) return;

    uint32_t xh[4][4];
    {   // prologue: X(t) -> half2 frags + illu(t) cp.async
        const float* xb = x + tile_base(t);
        #pragma unroll
        for (int kc = 0; kc < 4; kc++) ldxh(xb, kc, tq, g, xh[kc]);
        const float* ib = illu + tile_base(t);
        #pragma unroll
        for (int k = 0; k < 8; k++) {
            const int j = lane + k * 32, c = j >> 2, q = j & 3;
            cp_async16(sbIL + (uint32_t)(c * 80 + q * 16),
                       ib + (size_t)c * 65536 + q * 4);
        }
        cp_commit();
    }

    while (t < NWT) {
        const int tn = t + stride;
        const float* xbn = (tn < NWT) ? x + tile_base(tn) : x;

        // ---- GEMM1: acc1[px16][o64] = X^T @ Wm^T (single fp16) ----
        float acc1[8][4];
        #pragma unroll
        for (int nt = 0; nt < 8; nt++)
            #pragma unroll
            for (int q = 0; q < 4; q++) acc1[nt][q] = 0.0f;

        #pragma unroll
        for (int kc = 0; kc < 4; kc++) {
            uint32_t a[4] = { xh[kc][0], xh[kc][1], xh[kc][2], xh[kc][3] };
            #pragma unroll
            for (int ntp = 0; ntp < 4; ntp++) {
                uint32_t b[4];
                ldsm4(waddr(sbWM, ntp, kc, lane), b);
                mma16816(acc1[2 * ntp],     a, b[0], b[1]);
                mma16816(acc1[2 * ntp + 1], a, b[2], b[3]);
            }
            if (tn < NWT) ldxh(xbn, kc, tq, g, xh[kc]);  // prefetch, regs free
        }

        cp_wait<0>();
        __syncwarp();          // other lanes' illu(t) cp.async visible

        // ---- epilogue (T = illu * D1, fp16 in regs) fused with GEMM2 ----
        float acc2[8][4];
        #pragma unroll
        for (int nt = 0; nt < 8; nt++)
            #pragma unroll
            for (int q = 0; q < 4; q++) acc2[nt][q] = 0.0f;

        #pragma unroll
        for (int kc = 0; kc < 4; kc++) {
            const int nA = 2 * kc, nB = 2 * kc + 1;
            const int oa = nA * 8 + 2 * tq, ob_ = nB * 8 + 2 * tq;
            uint32_t a[4];
            a[0] = packh2(acc1[nA][0] * ILF[oa * 20 + g],
                          acc1[nA][1] * ILF[(oa + 1) * 20 + g]);
            a[1] = packh2(acc1[nA][2] * ILF[oa * 20 + g + 8],
                          acc1[nA][3] * ILF[(oa + 1) * 20 + g + 8]);
            a[2] = packh2(acc1[nB][0] * ILF[ob_ * 20 + g],
                          acc1[nB][1] * ILF[(ob_ + 1) * 20 + g]);
            a[3] = packh2(acc1[nB][2] * ILF[ob_ * 20 + g + 8],
                          acc1[nB][3] * ILF[(ob_ + 1) * 20 + g + 8]);
            #pragma unroll
            for (int ntp = 0; ntp < 4; ntp++) {
                uint32_t b[4];
                ldsm4(waddr(sbWP, ntp, kc, lane), b);
                mma16816(acc2[2 * ntp],     a, b[0], b[1]);
                mma16816(acc2[2 * ntp + 1], a, b[2], b[3]);
            }
        }
        __syncwarp();          // all lanes done reading illu(t)

        // prefetch illu(t+1)
        if (tn < NWT) {
            const float* ib = illu + tile_base(tn);
            #pragma unroll
            for (int k = 0; k < 8; k++) {
                const int j = lane + k * 32, c = j >> 2, q = j & 3;
                cp_async16(sbIL + (uint32_t)(c * 80 + q * 16),
                           ib + (size_t)c * 65536 + q * 4);
            }
            cp_commit();
        }

        // ---- store Y^T frags -> out[o'][px] ----
        {
            float* obp = out + tile_base(t);
            #pragma unroll
            for (int nt = 0; nt < 8; nt++) {
                float* q = obp + (size_t)(nt * 8 + 2 * tq) * 65536 + g;
                q[0]         = acc2[nt][0];
                q[65536]     = acc2[nt][1];
                q[8]         = acc2[nt][2];
                q[65536 + 8] = acc2[nt][3];
            }
        }
        t = tn;
    }
}

extern "C" void kernel_launch(void* const* d_in, const int* in_sizes, int n_in,
                              void* d_out, int out_size)
{
    const float* x      = (const float*)d_in[0];
    const float* illu   = (const float*)d_in[1];
    const float* wvspec = (const float*)d_in[4];
    const float* wvspat = (const float*)d_in[7];
    const float* wproj  = (const float*)d_in[10];
    float* out = (float*)d_out;

    int dev = 0, sms = 148;
    cudaGetDevice(&dev);
    cudaDeviceGetAttribute(&sms, cudaDevAttrMultiProcessorCount, dev);
    if (sms < 1) sms = 148;
    int grid = 2 * sms;
    if (grid * 8 > NWT) grid = NWT / 8;

    cudaFuncSetAttribute(fused_h1, cudaFuncAttributeMaxDynamicSharedMemorySize,
                         SM_TOTAL);
    fused_h1<<<grid, TPB, SM_TOTAL>>>(x, illu, wvspec, wvspat, wproj, out);
}